// round 2
// baseline (speedup 1.0000x reference)
#include <cuda_runtime.h>
#include <math.h>

#define SETS 32   // B*M
#define NI   128  // N
#define DD   32   // D
#define KK   64   // 2D
#define HH   64   // H
#define WP   36   // padded smem row stride (floats) -> conflict-free LDS.128
#define JT   8    // j-tile in k2

// Scratch (allocation-free rule: __device__ globals)
__device__ __align__(16) float g_x1[SETS * NI * DD];
__device__ __align__(16) float g_A [SETS * NI * KK];
__device__ __align__(16) float g_B [SETS * NI * KK];
__device__ float g_mask[SETS * NI];
__device__ float g_v2[KK];
__device__ float g_c2;

__device__ __forceinline__ float gelu_t(float x) {
    // jax.nn.gelu approximate=True
    float u = x * fmaf(0.044715f * 0.7978845608028654f, x * x, 0.7978845608028654f);
    float th;
    asm("tanh.approx.f32 %0, %1;" : "=f"(th) : "f"(u));
    float hx = 0.5f * x;
    return fmaf(hx, th, hx);
}

__device__ __forceinline__ float block_sum_128(float v, float* sh4) {
    #pragma unroll
    for (int o = 16; o > 0; o >>= 1) v += __shfl_down_sync(0xffffffffu, v, o);
    int lane = threadIdx.x & 31, w = threadIdx.x >> 5;
    if (lane == 0) sh4[w] = v;
    __syncthreads();
    float r = sh4[0] + sh4[1] + sh4[2] + sh4[3];
    __syncthreads();
    return r;
}

// ---- packed f32x2 helpers (FFMA2 path, PTX-only) ----
__device__ __forceinline__ unsigned long long pk2(float lo, float hi) {
    unsigned long long r;
    asm("mov.b64 %0, {%1,%2};" : "=l"(r) : "f"(lo), "f"(hi));
    return r;
}
#define ADD2(o,a,b)   asm("add.rn.f32x2 %0, %1, %2;"     : "=l"(o) : "l"(a), "l"(b))
#define MUL2(o,a,b)   asm("mul.rn.f32x2 %0, %1, %2;"     : "=l"(o) : "l"(a), "l"(b))
#define FMA2(o,a,b,c) asm("fma.rn.f32x2 %0, %1, %2, %3;" : "=l"(o) : "l"(a), "l"(b), "l"(c))

// acc2 += gelu(a2 + bneg2) * v2, elementwise on packed f32x2
__device__ __forceinline__ unsigned long long gelu2_dot(
    unsigned long long a2, unsigned long long bneg2, unsigned long long v2,
    unsigned long long acc2, unsigned long long C0_2, unsigned long long C1_2,
    unsigned long long H_2)
{
    unsigned long long t2, xx2, w2, u2, th2, hx2, g2;
    ADD2(t2, a2, bneg2);           // t = a - b
    MUL2(xx2, t2, t2);
    FMA2(w2, xx2, C1_2, C0_2);
    MUL2(u2, t2, w2);
    float u0, u1, t0, t1;
    asm("mov.b64 {%0,%1}, %2;" : "=f"(u0), "=f"(u1) : "l"(u2));
    asm("tanh.approx.f32 %0, %1;" : "=f"(t0) : "f"(u0));
    asm("tanh.approx.f32 %0, %1;" : "=f"(t1) : "f"(u1));
    asm("mov.b64 %0, {%1,%2};" : "=l"(th2) : "f"(t0), "f"(t1));
    MUL2(hx2, t2, H_2);
    FMA2(g2, hx2, th2, hx2);       // g = 0.5t*th + 0.5t
    FMA2(acc2, g2, v2, acc2);
    return acc2;
}

// Kernel 1: fused stats + set_norm + MLP1 + A/B precompute.
// Grid = SETS*4 blocks x 128 threads. Each block: one 32-row tile; thread
// (rl = tid>>2, p = tid&3) handles row rl with k-slice {k : k%4 == p}.
__global__ __launch_bounds__(128) void k1_prep(
    const float* __restrict__ x, const float* __restrict__ xsz,
    const float* __restrict__ W1a, const float* __restrict__ b1a,
    const float* __restrict__ W1b, const float* __restrict__ b1b,
    const float* __restrict__ W2a, const float* __restrict__ b2a,
    const float* __restrict__ W2b, const float* __restrict__ b2b,
    const float* __restrict__ w3)
{
    const int s    = blockIdx.x >> 2;
    const int tile = blockIdx.x & 3;
    const int tid  = threadIdx.x;

    __shared__ float red[4];
    __shared__ float sMkAll[NI];
    __shared__ __align__(16) float sW1aT[KK * WP];   // [k][d] transposed
    __shared__ __align__(16) float sW1b [KK * WP];   // [k][d]
    __shared__ __align__(16) float sW2aT[KK * WP];   // [k][d] transposed
    __shared__ float sb1a[KK], sb2a[KK], sb1b[DD];

    // stage weights (transpose W1a/W2a to [k][d], pad rows to WP)
    for (int i = tid; i < KK * DD; i += 128) {
        int k = i >> 5, d = i & 31;
        sW1aT[k * WP + d] = W1a[d * KK + k];
        sW2aT[k * WP + d] = W2a[d * KK + k];
        sW1b [k * WP + d] = W1b[i];
    }
    if (tid < KK) { sb1a[tid] = b1a[tid]; sb2a[tid] = b2a[tid]; }
    if (tid < DD) sb1b[tid] = b1b[tid];

    // ---- stats over the whole set: thread = row tid ----
    float lsum = 0.f; int anynz = 0;
    {
        const float4* xp = (const float4*)(x + ((size_t)s * NI + tid) * DD);
        #pragma unroll
        for (int q = 0; q < 8; q++) {
            float4 v = xp[q];
            lsum += v.x + v.y + v.z + v.w;
            anynz |= (v.x != 0.f) | (v.y != 0.f) | (v.z != 0.f) | (v.w != 0.f);
        }
    }
    const float mk_t = anynz ? 1.f : 0.f;
    sMkAll[tid] = mk_t;
    g_mask[s * NI + tid] = mk_t;

    const float denom = xsz[s >> 3] * (float)DD;
    const float tot   = block_sum_128(lsum, red);   // syncs cover staging too
    const float mean  = tot / denom;

    float lv = 0.f;
    {
        const float4* xp = (const float4*)(x + ((size_t)s * NI + tid) * DD);
        #pragma unroll
        for (int q = 0; q < 8; q++) {
            float4 v = xp[q];
            float a = v.x - mean, b = v.y - mean, c = v.z - mean, e = v.w - mean;
            lv += a * a + b * b + c * c + e * e;
        }
    }
    lv *= mk_t;
    const float var  = block_sum_128(lv, red);
    const float rstd = 1.f / (sqrtf(var / denom) + 1e-8f);

    // ---- per-thread assigned row ----
    const int rl  = tid >> 2;
    const int p   = tid & 3;
    const int row = tile * 32 + rl;
    const float mk  = sMkAll[row];
    const float inv = mk * rstd;

    float xn[DD];
    {
        const float4* xp = (const float4*)(x + ((size_t)s * NI + row) * DD);
        #pragma unroll
        for (int q = 0; q < 8; q++) {
            float4 v = xp[q];
            xn[4*q+0] = (v.x - mean) * inv;
            xn[4*q+1] = (v.y - mean) * inv;
            xn[4*q+2] = (v.z - mean) * inv;
            xn[4*q+3] = (v.w - mean) * inv;
        }
    }

    // MLP1: each thread does 16 of 64 hidden units (k = 4*kq + p)
    float x1p[DD];
    #pragma unroll
    for (int d = 0; d < DD; d++) x1p[d] = 0.f;

    #pragma unroll 4
    for (int kq = 0; kq < 16; kq++) {
        const int k = 4 * kq + p;
        const float4* wa = (const float4*)&sW1aT[k * WP];
        float aa = sb1a[k];
        #pragma unroll
        for (int q = 0; q < 8; q++) {
            float4 v = wa[q];
            aa = fmaf(xn[4*q+0], v.x, aa);
            aa = fmaf(xn[4*q+1], v.y, aa);
            aa = fmaf(xn[4*q+2], v.z, aa);
            aa = fmaf(xn[4*q+3], v.w, aa);
        }
        const float g = gelu_t(aa);
        const float4* wb = (const float4*)&sW1b[k * WP];
        #pragma unroll
        for (int q = 0; q < 8; q++) {
            float4 v = wb[q];
            x1p[4*q+0] = fmaf(g, v.x, x1p[4*q+0]);
            x1p[4*q+1] = fmaf(g, v.y, x1p[4*q+1]);
            x1p[4*q+2] = fmaf(g, v.z, x1p[4*q+2]);
            x1p[4*q+3] = fmaf(g, v.w, x1p[4*q+3]);
        }
    }
    // reduce the k-split across the 4 p-lanes (lane bits 0-1)
    #pragma unroll
    for (int d = 0; d < DD; d++) {
        x1p[d] += __shfl_xor_sync(0xffffffffu, x1p[d], 1);
        x1p[d] += __shfl_xor_sync(0xffffffffu, x1p[d], 2);
    }
    float x1[DD];
    #pragma unroll
    for (int d = 0; d < DD; d++) x1[d] = (x1p[d] + sb1b[d]) * mk;

    if (p == 0) {
        float4* px = (float4*)(g_x1 + ((size_t)s * NI + row) * DD);
        #pragma unroll
        for (int q = 0; q < 8; q++)
            px[q] = make_float4(x1[4*q], x1[4*q+1], x1[4*q+2], x1[4*q+3]);
    }

    // A[k] = b2a[k] + x1.W2a[:,k] ; B[k] = xn.W2a[:,k]  (shared weight load)
    float* pA = g_A + ((size_t)s * NI + row) * KK;
    float* pB = g_B + ((size_t)s * NI + row) * KK;
    #pragma unroll 4
    for (int kq = 0; kq < 16; kq++) {
        const int k = 4 * kq + p;
        const float4* wa = (const float4*)&sW2aT[k * WP];
        float a = sb2a[k], b = 0.f;
        #pragma unroll
        for (int q = 0; q < 8; q++) {
            float4 v = wa[q];
            a = fmaf(x1[4*q+0], v.x, a);  b = fmaf(xn[4*q+0], v.x, b);
            a = fmaf(x1[4*q+1], v.y, a);  b = fmaf(xn[4*q+1], v.y, b);
            a = fmaf(x1[4*q+2], v.z, a);  b = fmaf(xn[4*q+2], v.z, b);
            a = fmaf(x1[4*q+3], v.w, a);  b = fmaf(xn[4*q+3], v.w, b);
        }
        pA[k] = a;
        pB[k] = b;
    }

    // fold w3 through W2b/b2b (once)
    if (blockIdx.x == 0) {
        if (tid < KK) {
            float a = 0.f;
            for (int h = 0; h < HH; h++) a = fmaf(W2b[tid * HH + h], w3[h], a);
            g_v2[tid] = a;
        }
        if (tid == KK) {
            float a = 0.f;
            for (int h = 0; h < HH; h++) a = fmaf(b2b[h], w3[h], a);
            g_c2 = a;
        }
    }
}

// Kernel 2: pairwise gelu-dot (packed f32x2) + aggregation.
// Grid = SETS*16 blocks (j-tiles of 8) x 128 threads; thread = row i.
__global__ __launch_bounds__(128) void k2_pair(
    const float* __restrict__ x, const float* __restrict__ b3,
    float* __restrict__ out)
{
    const int blk = blockIdx.x;
    const int s   = blk >> 4;
    const int j0  = (blk & 15) * JT;
    const int tid = threadIdx.x;

    __shared__ __align__(16) float sBneg[JT * KK];  // negated B rows
    __shared__ __align__(16) float sV[KK];
    __shared__ __align__(16) float sX1[NI * DD];
    __shared__ __align__(16) float sS[JT * NI];
    __shared__ float sMk[JT];
    __shared__ float sc2;

    const float* pB = g_B + ((size_t)s * NI + j0) * KK;
    for (int i = tid; i < JT * KK; i += 128) sBneg[i] = -pB[i];
    {
        const float4* pX1 = (const float4*)(g_x1 + (size_t)s * NI * DD);
        float4* sX14 = (float4*)sX1;
        for (int i = tid; i < NI * DD / 4; i += 128) sX14[i] = pX1[i];
    }
    if (tid < KK) sV[tid] = g_v2[tid];
    if (tid == KK) sc2 = g_c2;
    if (tid < JT) sMk[tid] = g_mask[s * NI + j0 + tid];

    // A row -> packed registers (32 x f32x2)
    unsigned long long a2[KK / 2];
    {
        const ulonglong2* pA = (const ulonglong2*)(g_A + ((size_t)s * NI + tid) * KK);
        #pragma unroll
        for (int t = 0; t < 16; t++) {
            ulonglong2 v = pA[t];
            a2[2*t] = v.x; a2[2*t+1] = v.y;
        }
    }
    __syncthreads();

    const unsigned long long C0_2 = pk2(0.7978845608028654f, 0.7978845608028654f);
    const unsigned long long C1_2 = pk2(0.044715f * 0.7978845608028654f,
                                        0.044715f * 0.7978845608028654f);
    const unsigned long long H_2  = pk2(0.5f, 0.5f);
    const float c2 = sc2;
    const ulonglong2* vp2 = (const ulonglong2*)sV;

    #pragma unroll
    for (int jj = 0; jj < 2; jj++) {
        unsigned long long acc2[4];
        #pragma unroll
        for (int m = 0; m < 4; m++) acc2[m] = pk2(0.f, 0.f);
        #pragma unroll 4
        for (int q = 0; q < 16; q++) {          // 4 k per step
            ulonglong2 vv = vp2[q];             // v2 reused across 4 j's
            #pragma unroll
            for (int m = 0; m < 4; m++) {
                ulonglong2 bb = ((const ulonglong2*)(sBneg + (jj * 4 + m) * KK))[q];
                acc2[m] = gelu2_dot(a2[2*q],   bb.x, vv.x, acc2[m], C0_2, C1_2, H_2);
                acc2[m] = gelu2_dot(a2[2*q+1], bb.y, vv.y, acc2[m], C0_2, C1_2, H_2);
            }
        }
        #pragma unroll
        for (int m = 0; m < 4; m++) {
            float lo, hi;
            asm("mov.b64 {%0,%1}, %2;" : "=f"(lo), "=f"(hi) : "l"(acc2[m]));
            sS[(jj * 4 + m) * NI + tid] = lo + hi + c2;
        }
    }
    __syncthreads();

    // out[j,d] = sum_i S[j,i] * x1[i,d]  (+ b3 + x) * mask
    const int d = tid & 31;
    const int w = tid >> 5;
    const float b3v = b3[0];
    #pragma unroll
    for (int r = 0; r < 2; r++) {
        const int j = r * 4 + w;
        float acc = 0.f;
        const float* srow = &sS[j * NI];
        #pragma unroll 8
        for (int i = 0; i < NI; i++) acc = fmaf(srow[i], sX1[i * DD + d], acc);
        const int jg = j0 + j;
        const size_t oidx = ((size_t)s * NI + jg) * DD + d;
        out[oidx] = (acc + b3v + x[oidx]) * sMk[j];
    }
}

extern "C" void kernel_launch(void* const* d_in, const int* in_sizes, int n_in,
                              void* d_out, int out_size) {
    const float* x    = (const float*)d_in[0];
    const float* xsz  = (const float*)d_in[1];
    const float* W1a  = (const float*)d_in[2];
    const float* b1a  = (const float*)d_in[3];
    const float* W1b  = (const float*)d_in[4];
    const float* b1b  = (const float*)d_in[5];
    const float* W2a  = (const float*)d_in[6];
    const float* b2a  = (const float*)d_in[7];
    const float* W2b  = (const float*)d_in[8];
    const float* b2b  = (const float*)d_in[9];
    const float* w3   = (const float*)d_in[10];
    const float* b3   = (const float*)d_in[11];
    float* out = (float*)d_out;

    k1_prep<<<SETS * 4, 128>>>(x, xsz, W1a, b1a, W1b, b1b, W2a, b2a, W2b, b2b, w3);
    k2_pair<<<SETS * 16, 128>>>(x, b3, out);
}

// round 4
// speedup vs baseline: 1.7536x; 1.7536x over previous
#include <cuda_runtime.h>
#include <math.h>

#define SETS 32   // B*M
#define NI   128  // N
#define DD   32   // D
#define KK   64   // 2D
#define HH   64   // H
#define WPA  65   // padded row stride for [d][64] weight tiles
#define WPB  33   // padded row stride for [k][32] weight tile
#define JT   8    // j-tile in k2

// Scratch (allocation-free rule: __device__ globals)
__device__ __align__(16) float g_x1  [SETS * NI * DD];
__device__ __align__(16) float g_A   [SETS * NI * KK];
__device__ __align__(16) float g_Bneg[SETS * NI * KK];
__device__ float g_mask[SETS * NI];
__device__ float g_v2[KK];
__device__ float g_c2;

__device__ __forceinline__ float gelu_t(float x) {
    // jax.nn.gelu approximate=True
    float u = x * fmaf(0.044715f * 0.7978845608028654f, x * x, 0.7978845608028654f);
    float th;
    asm("tanh.approx.f32 %0, %1;" : "=f"(th) : "f"(u));
    float hx = 0.5f * x;
    return fmaf(hx, th, hx);
}

__device__ __forceinline__ float block_sum_128(float v, float* sh4) {
    #pragma unroll
    for (int o = 16; o > 0; o >>= 1) v += __shfl_down_sync(0xffffffffu, v, o);
    int lane = threadIdx.x & 31, w = threadIdx.x >> 5;
    if (lane == 0) sh4[w] = v;
    __syncthreads();
    float r = sh4[0] + sh4[1] + sh4[2] + sh4[3];
    __syncthreads();
    return r;
}

// ---- packed f32x2 helpers ----
__device__ __forceinline__ unsigned long long pk2(float lo, float hi) {
    unsigned long long r;
    asm("mov.b64 %0, {%1,%2};" : "=l"(r) : "f"(lo), "f"(hi));
    return r;
}
#define ADD2(o,a,b)   asm("add.rn.f32x2 %0, %1, %2;"     : "=l"(o) : "l"(a), "l"(b))
#define MUL2(o,a,b)   asm("mul.rn.f32x2 %0, %1, %2;"     : "=l"(o) : "l"(a), "l"(b))
#define FMA2(o,a,b,c) asm("fma.rn.f32x2 %0, %1, %2, %3;" : "=l"(o) : "l"(a), "l"(b), "l"(c))

// acc2 += gelu(a2 + bneg2) * v2   (packed f32x2)
__device__ __forceinline__ unsigned long long gelu2_dot(
    unsigned long long a2, unsigned long long bneg2, unsigned long long v2,
    unsigned long long acc2, unsigned long long C0_2, unsigned long long C1_2,
    unsigned long long H_2)
{
    unsigned long long t2, xx2, w2, u2, th2, hx2, g2;
    ADD2(t2, a2, bneg2);
    MUL2(xx2, t2, t2);
    FMA2(w2, xx2, C1_2, C0_2);
    MUL2(u2, t2, w2);
    float u0, u1, t0, t1;
    asm("mov.b64 {%0,%1}, %2;" : "=f"(u0), "=f"(u1) : "l"(u2));
    asm("tanh.approx.f32 %0, %1;" : "=f"(t0) : "f"(u0));
    asm("tanh.approx.f32 %0, %1;" : "=f"(t1) : "f"(u1));
    asm("mov.b64 %0, {%1,%2};" : "=l"(th2) : "f"(t0), "f"(t1));
    MUL2(hx2, t2, H_2);
    FMA2(g2, hx2, th2, hx2);
    FMA2(acc2, g2, v2, acc2);
    return acc2;
}

// Kernel 1: stats + set_norm + MLP1 + A/Bneg precompute.
// Grid = SETS*8 x 128 threads. Thread (rl = tid>>3, p = tid&7): row rl of a
// 16-row tile, k-slice {k : k%8 == p}.
__global__ __launch_bounds__(128) void k1_prep(
    const float* __restrict__ x, const float* __restrict__ xsz,
    const float* __restrict__ W1a, const float* __restrict__ b1a,
    const float* __restrict__ W1b, const float* __restrict__ b1b,
    const float* __restrict__ W2a, const float* __restrict__ b2a,
    const float* __restrict__ W2b, const float* __restrict__ b2b,
    const float* __restrict__ w3)
{
    const int s    = blockIdx.x >> 3;
    const int tile = blockIdx.x & 7;
    const int tid  = threadIdx.x;

    __shared__ float red[4];
    __shared__ float sMkAll[NI];
    __shared__ float sW1a[DD * WPA];   // natural [d][k], padded
    __shared__ float sW2a[DD * WPA];   // natural [d][k], padded
    __shared__ float sW1b[KK * WPB];   // natural [k][d], padded
    __shared__ float sb1a[KK], sb2a[KK], sb1b[DD];

    // stage weights: coalesced reads, conflict-free padded stores
    for (int i = tid; i < KK * DD; i += 128) {
        int d = i >> 6, k = i & 63;          // W1a/W2a linear = d*64+k
        sW1a[d * WPA + k] = W1a[i];
        sW2a[d * WPA + k] = W2a[i];
        int kb = i >> 5, db = i & 31;        // W1b linear = k*32+d
        sW1b[kb * WPB + db] = W1b[i];
    }
    if (tid < KK) { sb1a[tid] = b1a[tid]; sb2a[tid] = b2a[tid]; }
    if (tid < DD) sb1b[tid] = b1b[tid];

    // ---- stats over the whole set (thread = row tid) ----
    float lsum = 0.f; int anynz = 0;
    {
        const float4* xp = (const float4*)(x + ((size_t)s * NI + tid) * DD);
        #pragma unroll
        for (int q = 0; q < 8; q++) {
            float4 v = xp[q];
            lsum += v.x + v.y + v.z + v.w;
            anynz |= (v.x != 0.f) | (v.y != 0.f) | (v.z != 0.f) | (v.w != 0.f);
        }
    }
    const float mk_t = anynz ? 1.f : 0.f;
    sMkAll[tid] = mk_t;
    g_mask[s * NI + tid] = mk_t;

    const float denom = xsz[s >> 3] * (float)DD;
    const float tot   = block_sum_128(lsum, red);  // internal syncs also cover staging
    const float mean  = tot / denom;

    float lv = 0.f;
    {
        const float4* xp = (const float4*)(x + ((size_t)s * NI + tid) * DD);
        #pragma unroll
        for (int q = 0; q < 8; q++) {
            float4 v = xp[q];
            float a = v.x - mean, b = v.y - mean, c = v.z - mean, e = v.w - mean;
            lv += a * a + b * b + c * c + e * e;
        }
    }
    lv *= mk_t;
    const float var  = block_sum_128(lv, red);
    const float rstd = 1.f / (sqrtf(var / denom) + 1e-8f);

    // ---- per-thread row/k-slice ----
    const int p   = tid & 7;
    const int rl  = tid >> 3;
    const int row = tile * 16 + rl;
    const float mk  = sMkAll[row];
    const float inv = mk * rstd;

    float xn[DD];
    {
        const float4* xp = (const float4*)(x + ((size_t)s * NI + row) * DD);
        #pragma unroll
        for (int q = 0; q < 8; q++) {
            float4 v = xp[q];
            xn[4*q+0] = (v.x - mean) * inv;
            xn[4*q+1] = (v.y - mean) * inv;
            xn[4*q+2] = (v.z - mean) * inv;
            xn[4*q+3] = (v.w - mean) * inv;
        }
    }

    // MLP1: 8 hidden units per thread (k = 8*kq + p)
    float x1p[DD];
    #pragma unroll
    for (int d = 0; d < DD; d++) x1p[d] = 0.f;

    #pragma unroll
    for (int kq = 0; kq < 8; kq++) {
        const int k = 8 * kq + p;
        float aa = sb1a[k];
        #pragma unroll
        for (int d = 0; d < DD; d++) aa = fmaf(xn[d], sW1a[d * WPA + k], aa);
        const float g = gelu_t(aa);
        #pragma unroll
        for (int d = 0; d < DD; d++) x1p[d] = fmaf(g, sW1b[k * WPB + d], x1p[d]);
    }
    // reduce k-split over the 8 p-lanes (lane bits 0-2)
    #pragma unroll
    for (int d = 0; d < DD; d++) {
        x1p[d] += __shfl_xor_sync(0xffffffffu, x1p[d], 1);
        x1p[d] += __shfl_xor_sync(0xffffffffu, x1p[d], 2);
        x1p[d] += __shfl_xor_sync(0xffffffffu, x1p[d], 4);
    }
    float x1[DD];
    #pragma unroll
    for (int d = 0; d < DD; d++) x1[d] = (x1p[d] + sb1b[d]) * mk;

    if (p == 0) {
        float4* px = (float4*)(g_x1 + ((size_t)s * NI + row) * DD);
        #pragma unroll
        for (int q = 0; q < 8; q++)
            px[q] = make_float4(x1[4*q], x1[4*q+1], x1[4*q+2], x1[4*q+3]);
    }

    // A[k] = b2a[k] + x1.W2a[:,k] ; Bneg[k] = -(xn.W2a[:,k])
    float* pA = g_A    + ((size_t)s * NI + row) * KK;
    float* pB = g_Bneg + ((size_t)s * NI + row) * KK;
    #pragma unroll
    for (int kq = 0; kq < 8; kq++) {
        const int k = 8 * kq + p;
        float a = sb2a[k], b = 0.f;
        #pragma unroll
        for (int d = 0; d < DD; d++) {
            float w = sW2a[d * WPA + k];
            a = fmaf(x1[d], w, a);
            b = fmaf(xn[d], w, b);
        }
        pA[k] = a;
        pB[k] = -b;
    }

    // fold w3 through W2b/b2b (once)
    if (blockIdx.x == 0) {
        if (tid < KK) {
            float a = 0.f;
            for (int h = 0; h < HH; h++) a = fmaf(W2b[tid * HH + h], w3[h], a);
            g_v2[tid] = a;
        }
        if (tid == KK) {
            float a = 0.f;
            for (int h = 0; h < HH; h++) a = fmaf(b2b[h], w3[h], a);
            g_c2 = a;
        }
    }
}

// Kernel 2: pairwise gelu-dot (packed f32x2, fully static unroll) + aggregation.
// Grid = SETS*16 blocks (j-tiles of 8) x 128 threads; thread = row i.
__global__ __launch_bounds__(128) void k2_pair(
    const float* __restrict__ x, const float* __restrict__ b3,
    float* __restrict__ out)
{
    const int blk = blockIdx.x;
    const int s   = blk >> 4;
    const int j0  = (blk & 15) * JT;
    const int tid = threadIdx.x;

    __shared__ __align__(16) float sBneg[JT * KK];
    __shared__ __align__(16) float sV[KK];
    __shared__ __align__(16) float sX1[NI * DD];
    __shared__ __align__(16) float sS[JT * NI];
    __shared__ float sMk[JT];
    __shared__ float sc2;

    {
        const float4* pB = (const float4*)(g_Bneg + ((size_t)s * NI + j0) * KK);
        float4* sB4 = (float4*)sBneg;
        for (int i = tid; i < JT * KK / 4; i += 128) sB4[i] = pB[i];
        const float4* pX1 = (const float4*)(g_x1 + (size_t)s * NI * DD);
        float4* sX14 = (float4*)sX1;
        for (int i = tid; i < NI * DD / 4; i += 128) sX14[i] = pX1[i];
    }
    if (tid < KK) sV[tid] = g_v2[tid];
    if (tid == KK) sc2 = g_c2;
    if (tid < JT) sMk[tid] = g_mask[s * NI + j0 + tid];

    const bool iactive = (g_mask[s * NI + tid] != 0.f);

    // A row -> packed registers (fully static indexing — MUST stay in regs)
    unsigned long long a2[KK / 2];
    {
        const ulonglong2* pA = (const ulonglong2*)(g_A + ((size_t)s * NI + tid) * KK);
        #pragma unroll
        for (int t = 0; t < 16; t++) {
            ulonglong2 v = pA[t];
            a2[2*t] = v.x; a2[2*t+1] = v.y;
        }
    }
    __syncthreads();

    const unsigned long long C0_2 = pk2(0.7978845608028654f, 0.7978845608028654f);
    const unsigned long long C1_2 = pk2(0.044715f * 0.7978845608028654f,
                                        0.044715f * 0.7978845608028654f);
    const unsigned long long H_2  = pk2(0.5f, 0.5f);
    const float c2 = sc2;
    const ulonglong2* vp2 = (const ulonglong2*)sV;

    #pragma unroll 1
    for (int jj = 0; jj < 2; jj++) {
        const float jsum = sMk[jj*4+0] + sMk[jj*4+1] + sMk[jj*4+2] + sMk[jj*4+3];
        const bool act = iactive && (jsum != 0.f);
        unsigned long long acc2[4];
        #pragma unroll
        for (int m = 0; m < 4; m++) acc2[m] = 0ull;
        if (act) {
            #pragma unroll
            for (int q = 0; q < 16; q++) {            // FULL unroll: static a2 idx
                ulonglong2 vv = vp2[q];
                #pragma unroll
                for (int m = 0; m < 4; m++) {
                    ulonglong2 bb = ((const ulonglong2*)(sBneg + (jj*4 + m) * KK))[q];
                    acc2[m] = gelu2_dot(a2[2*q],   bb.x, vv.x, acc2[m], C0_2, C1_2, H_2);
                    acc2[m] = gelu2_dot(a2[2*q+1], bb.y, vv.y, acc2[m], C0_2, C1_2, H_2);
                }
            }
        }
        #pragma unroll
        for (int m = 0; m < 4; m++) {
            float lo, hi;
            asm("mov.b64 {%0,%1}, %2;" : "=f"(lo), "=f"(hi) : "l"(acc2[m]));
            sS[(jj*4 + m) * NI + tid] = act ? (lo + hi + c2) : 0.f;
        }
    }
    __syncthreads();

    // out[j,d] = sum_i S[j,i] * x1[i,d]  (+ b3 + x) * mask
    const int d = tid & 31;
    const int w = tid >> 5;
    const float b3v = b3[0];
    #pragma unroll
    for (int r = 0; r < 2; r++) {
        const int j = r * 4 + w;
        float acc = 0.f;
        const float* srow = &sS[j * NI];
        #pragma unroll 8
        for (int i = 0; i < NI; i++) acc = fmaf(srow[i], sX1[i * DD + d], acc);
        const int jg = j0 + j;
        const size_t oidx = ((size_t)s * NI + jg) * DD + d;
        out[oidx] = (acc + b3v + x[oidx]) * sMk[j];
    }
}

extern "C" void kernel_launch(void* const* d_in, const int* in_sizes, int n_in,
                              void* d_out, int out_size) {
    const float* x    = (const float*)d_in[0];
    const float* xsz  = (const float*)d_in[1];
    const float* W1a  = (const float*)d_in[2];
    const float* b1a  = (const float*)d_in[3];
    const float* W1b  = (const float*)d_in[4];
    const float* b1b  = (const float*)d_in[5];
    const float* W2a  = (const float*)d_in[6];
    const float* b2a  = (const float*)d_in[7];
    const float* W2b  = (const float*)d_in[8];
    const float* b2b  = (const float*)d_in[9];
    const float* w3   = (const float*)d_in[10];
    const float* b3   = (const float*)d_in[11];
    float* out = (float*)d_out;

    k1_prep<<<SETS * 8, 128>>>(x, xsz, W1a, b1a, W1b, b1b, W2a, b2a, W2b, b2b, w3);
    k2_pair<<<SETS * 16, 128>>>(x, b3, out);
}